// round 4
// baseline (speedup 1.0000x reference)
#include <cuda_runtime.h>
#include <stdint.h>

#define NTHREADS 1024
#define NWARPS (NTHREADS / 32)
#define HBITS 13
#define NBINS (1 << HBITS)
#define BPT (NBINS / NTHREADS)      // bins per thread = 8
#define CAP 2048                    // candidate buffer per row
#define NEED_S 330                  // suffix target in SAMPLES (1-of-4 subsample)
#define SAMPLING_EPS 1e-5f

// order-preserving float -> uint32 map (and inverse)
__device__ __forceinline__ unsigned mono(float f) {
    unsigned u = __float_as_uint(f);
    return u ^ ((unsigned)(((int)u) >> 31) | 0x80000000u);
}
__device__ __forceinline__ float inv_mono(unsigned m) {
    unsigned u = (m & 0x80000000u) ? (m ^ 0x80000000u) : ~m;
    return __uint_as_float(u);
}

// combine two (max, sumexp) pairs: (m,s) <- (m,s) ⊕ (om,os)
__device__ __forceinline__ void lse_comb(float& m, float& s, float om, float os) {
    if (om > m)      { s = os + s * __expf(m - om); m = om; }
    else if (om > -1e37f) { s += os * __expf(om - m); }
}

// one bitonic round's register-resident phases (j = jstart..1, jstart<=32).
// thread holds elements a at index i0 = 64*warp+lane, b at i1 = i0+32.
__device__ __forceinline__ void reg_round(unsigned long long& a, unsigned long long& b,
                                          int i0, int i1, int lane, int kk, int jstart) {
    const bool upa = ((i0 & kk) == 0);
    const bool upb = ((i1 & kk) == 0);
#pragma unroll
    for (int j = 32; j >= 1; j >>= 1) {
        if (j > jstart) continue;
        if (j == 32) {
            // in-thread pair (i0, i0+32); lower index is i0 -> direction upa
            unsigned long long lo = a < b ? a : b;
            unsigned long long hi = a < b ? b : a;
            a = upa ? lo : hi;
            b = upa ? hi : lo;
        } else {
            const bool lower = ((lane & j) == 0);
            unsigned long long pa = __shfl_xor_sync(0xFFFFFFFFu, a, j);
            unsigned long long pb = __shfl_xor_sync(0xFFFFFFFFu, b, j);
            bool keepMinA = (lower == upa);
            bool keepMinB = (lower == upb);
            a = keepMinA ? (a < pa ? a : pa) : (a > pa ? a : pa);
            b = keepMinB ? (b < pb ? b : pb) : (b > pb ? b : pb);
        }
    }
}

// ======================================================================
// Fused sampler: per row (1 CTA):
//   pass A (DRAM): max + online log-sum-exp + 1/4-subsampled 13-bit histogram
//   shuffle scans -> candidate threshold
//   pass B (L2-hot): candidate collection only
//   hybrid bitonic sort (warp-shuffle inner phases), min-p/top-k/top-p,
//   exponential-race sampling, top-20 logprobs, rank
// ======================================================================
__global__ __launch_bounds__(NTHREADS, 1) void sampler_fused(
    const float* __restrict__ logits,
    const float* __restrict__ temperature,
    const float* __restrict__ min_p,
    const int*   __restrict__ top_k,
    const float* __restrict__ top_p,
    const float* __restrict__ q,
    float* __restrict__ out,
    int B, int V, int C)
{
    const int row = blockIdx.x;
    const int t = threadIdx.x;
    const int lane = t & 31, warp = t >> 5;

    // 32KB buffer: phase A = hist[8192 u32]; phase B+ = key[2048 u64] | e[2048 f32] | hd[2048 f32]
    __shared__ __align__(16) unsigned char sbuf[NBINS * 4];
    __shared__ float wm[NWARPS], ws[NWARPS], wf[NWARPS];
    __shared__ unsigned wu[NWARPS];
    __shared__ int wi[NWARPS], wr[NWARPS];
    __shared__ unsigned s_bin;
    __shared__ int s_cnt, s_m, s_S, s_rank, s_sampled, s_rstar;
    __shared__ float s_stat[2];   // [0]=rmax [1]=logZ

    unsigned* hist = (unsigned*)sbuf;

    if (t == 0) { s_cnt = 0; s_m = 0; s_S = 0; s_rank = 0; s_bin = 0; }
#pragma unroll
    for (int z = t; z < NBINS; z += NTHREADS) hist[z] = 0u;
    __syncthreads();

    const float* __restrict__ x = logits + (size_t)row * V;
    const int V4 = V >> 2;
    const float4* __restrict__ x4 = (const float4*)x;
    const float NEG_INF = __int_as_float(0xff800000);

    // ---------------- pass A: max + LSE + subsampled histogram -----------------
    float pm0 = NEG_INF, pm1 = NEG_INF, pm2 = NEG_INF, pm3 = NEG_INF;
    float ps0 = 0.f, ps1 = 0.f, ps2 = 0.f, ps3 = 0.f;
    auto procA = [&](float4 v) {
        // 1-of-4 subsampled histogram (element index ≡ 0 mod 4)
        atomicAdd(&hist[mono(v.x) >> (32 - HBITS)], 1u);
        // branchy online LSE, 4 independent accumulators
        if (v.x > pm0) { ps0 = ps0 * __expf(pm0 - v.x) + 1.f; pm0 = v.x; } else ps0 += __expf(v.x - pm0);
        if (v.y > pm1) { ps1 = ps1 * __expf(pm1 - v.y) + 1.f; pm1 = v.y; } else ps1 += __expf(v.y - pm1);
        if (v.z > pm2) { ps2 = ps2 * __expf(pm2 - v.z) + 1.f; pm2 = v.z; } else ps2 += __expf(v.z - pm2);
        if (v.w > pm3) { ps3 = ps3 * __expf(pm3 - v.w) + 1.f; pm3 = v.w; } else ps3 += __expf(v.w - pm3);
    };
    int i = t;
    for (; i + 3 * NTHREADS < V4; i += 4 * NTHREADS) {
        float4 a = x4[i];
        float4 b = x4[i + NTHREADS];
        float4 c = x4[i + 2 * NTHREADS];
        float4 d = x4[i + 3 * NTHREADS];
        procA(a); procA(b); procA(c); procA(d);
    }
    for (; i < V4; i += NTHREADS) procA(x4[i]);
    for (int j = (V4 << 2) + t; j < V; j += NTHREADS) {
        float v = x[j];
        atomicAdd(&hist[mono(v) >> (32 - HBITS)], 1u);
        if (v > pm0) { ps0 = ps0 * __expf(pm0 - v) + 1.f; pm0 = v; } else ps0 += __expf(v - pm0);
    }

    // merge 4 accumulators, then warp/block reduce
    lse_comb(pm0, ps0, pm1, ps1);
    lse_comb(pm2, ps2, pm3, ps3);
    lse_comb(pm0, ps0, pm2, ps2);
#pragma unroll
    for (int off = 16; off; off >>= 1) {
        float om = __shfl_xor_sync(0xFFFFFFFFu, pm0, off);
        float os = __shfl_xor_sync(0xFFFFFFFFu, ps0, off);
        lse_comb(pm0, ps0, om, os);
    }
    if (lane == 0) { wm[warp] = pm0; ws[warp] = ps0; }
    __syncthreads();                       // hist complete + wm/ws visible
    if (warp == 0) {
        float mm = wm[lane], ss = ws[lane];
#pragma unroll
        for (int off = 16; off; off >>= 1) {
            float om = __shfl_xor_sync(0xFFFFFFFFu, mm, off);
            float os = __shfl_xor_sync(0xFFFFFFFFu, ss, off);
            lse_comb(mm, ss, om, os);
        }
        if (lane == 0) { s_stat[0] = mm; s_stat[1] = mm + logf(ss); }
    }

    // ---------------- threshold from histogram (shuffle suffix scan) ----------
    unsigned csum = 0;
#pragma unroll
    for (int b = 0; b < BPT; b++) csum += hist[t * BPT + b];
    unsigned iv = csum;
#pragma unroll
    for (int off = 1; off < 32; off <<= 1) {
        unsigned nb = __shfl_up_sync(0xFFFFFFFFu, iv, off);
        if (lane >= off) iv += nb;
    }
    if (lane == 31) wu[warp] = iv;
    __syncthreads();                       // also publishes s_stat
    if (warp == 0) {
        unsigned wv = wu[lane];
#pragma unroll
        for (int off = 1; off < 32; off <<= 1) {
            unsigned nb = __shfl_up_sync(0xFFFFFFFFu, wv, off);
            if (lane >= off) wv += nb;
        }
        wu[lane] = wv;
    }
    __syncthreads();
    unsigned incl = iv + (warp ? wu[warp - 1] : 0u);
    unsigned Total = wu[NWARPS - 1];
    unsigned above = Total - incl;         // samples strictly above my chunk
    unsigned acc = above, prev = above;
#pragma unroll
    for (int b = BPT - 1; b >= 0; b--) {
        int bin = t * BPT + b;
        acc += hist[bin];                  // = suffix(bin) in samples
        if (acc >= NEED_S && prev < NEED_S) s_bin = (unsigned)bin;  // unique crossing
        prev = acc;
    }
    __syncthreads();
    const unsigned thr = s_bin << (32 - HBITS);
    const float rmax = s_stat[0];
    const float lZ   = s_stat[1];

    // ---------------- pass B: collect candidates (L2-hot) ---------------------
    unsigned long long* key = (unsigned long long*)sbuf;       // overwrites hist
    float* e  = (float*)(sbuf + CAP * 8);
    float* hd = (float*)(sbuf + CAP * 8 + CAP * 4);

    auto procB = [&](float4 v, int base) {
        unsigned u;
        u = mono(v.x); if (u >= thr) { int p = atomicAdd(&s_cnt, 1); if (p < CAP) key[p] = ((unsigned long long)u << 32) | (unsigned)~(unsigned)(base + 0); }
        u = mono(v.y); if (u >= thr) { int p = atomicAdd(&s_cnt, 1); if (p < CAP) key[p] = ((unsigned long long)u << 32) | (unsigned)~(unsigned)(base + 1); }
        u = mono(v.z); if (u >= thr) { int p = atomicAdd(&s_cnt, 1); if (p < CAP) key[p] = ((unsigned long long)u << 32) | (unsigned)~(unsigned)(base + 2); }
        u = mono(v.w); if (u >= thr) { int p = atomicAdd(&s_cnt, 1); if (p < CAP) key[p] = ((unsigned long long)u << 32) | (unsigned)~(unsigned)(base + 3); }
    };
    i = t;
    for (; i + 3 * NTHREADS < V4; i += 4 * NTHREADS) {
        float4 a = x4[i];
        float4 b = x4[i + NTHREADS];
        float4 c = x4[i + 2 * NTHREADS];
        float4 d = x4[i + 3 * NTHREADS];
        procB(a, 4 * i);
        procB(b, 4 * (i + NTHREADS));
        procB(c, 4 * (i + 2 * NTHREADS));
        procB(d, 4 * (i + 3 * NTHREADS));
    }
    for (; i < V4; i += NTHREADS) procB(x4[i], 4 * i);
    for (int j = (V4 << 2) + t; j < V; j += NTHREADS) {
        unsigned u = mono(x[j]);
        if (u >= thr) { int p = atomicAdd(&s_cnt, 1); if (p < CAP) key[p] = ((unsigned long long)u << 32) | (unsigned)~(unsigned)j; }
    }
    __syncthreads();
    const int n = min(s_cnt, CAP);
    for (int z = n + t; z < CAP; z += NTHREADS) key[z] = 0ULL;  // sentinel
    __syncthreads();

    // ---------------- hybrid bitonic sort (ascending) --------------------------
    const int i0 = 64 * warp + lane;
    const int i1 = i0 + 32;
    {
        unsigned long long a = key[i0], b = key[i1];
        // rounds kk = 2..64 fully register-resident (no barriers)
#pragma unroll
        for (int kk = 2; kk <= 64; kk <<= 1)
            reg_round(a, b, i0, i1, lane, kk, kk > 64 ? 32 : (kk >> 1) > 32 ? 32 : (kk >> 1));
        key[i0] = a; key[i1] = b;
        __syncthreads();
        // rounds kk = 128..CAP: smem phases j>=64, then register phases j<=32
        for (int kk = 128; kk <= CAP; kk <<= 1) {
            for (int j = kk >> 1; j >= 64; j >>= 1) {
#pragma unroll
                for (int w2 = 0; w2 < CAP / NTHREADS; w2++) {
                    int idx = t + w2 * NTHREADS;
                    int l2 = idx ^ j;
                    if (l2 > idx) {
                        unsigned long long av = key[idx], bv = key[l2];
                        bool sw = ((idx & kk) == 0) ? (av > bv) : (av < bv);
                        if (sw) { key[idx] = bv; key[l2] = av; }
                    }
                }
                __syncthreads();
            }
            a = key[i0]; b = key[i1];
            reg_round(a, b, i0, i1, lane, kk, 32);
            key[i0] = a; key[i1] = b;
            __syncthreads();
        }
    }

#define DKEY(r) (key[CAP - 1 - (r)])
#define DVAL(r) inv_mono((unsigned)(DKEY(r) >> 32))
#define DIDX(r) ((int)(~(unsigned)DKEY(r)))

    // ---------------- per-row scalars ----------------
    const float temp = temperature[row];
    const float mp   = min_p[row];
    const float tp   = top_p[row];
    int kk_ = top_k[row];
    kk_ = max(1, min(kk_, V));
    const float t_mp = rmax + temp * logf(mp);   // min-p threshold in logit space

    // m = # min-p survivors among candidates
    for (int r = t; r < n; r += NTHREADS)
        if (DVAL(r) >= t_mp) atomicAdd(&s_m, 1);
    __syncthreads();
    const int mcnt = s_m;

    // S = # survivors after top-k
    if (mcnt >= kk_) {
        float kth = DVAL(kk_ - 1);
        for (int r = t; r < n; r += NTHREADS)
            if (DVAL(r) >= kth) atomicAdd(&s_S, 1);
    }
    __syncthreads();
    const int S = (mcnt >= kk_) ? min(s_S, CAP) : mcnt;

    const bool greedy = (temp < SAMPLING_EPS);
    int sampled, rstar;

    if (!greedy) {
        // softmax numerators over survivors
        const float lt0 = DVAL(0) / temp;
        for (int r = t; r < CAP; r += NTHREADS) {
            float ev = 0.f;
            if (r < S) ev = expf(DVAL(r) / temp - lt0);
            e[r] = ev;
        }
        __syncthreads();

        // exclusive prefix over descending order (shuffle scan)
        float a0 = e[2 * t], a1 = e[2 * t + 1];
        float tsum = a0 + a1;
        float sv = tsum;
#pragma unroll
        for (int off = 1; off < 32; off <<= 1) {
            float nb = __shfl_up_sync(0xFFFFFFFFu, sv, off);
            if (lane >= off) sv += nb;
        }
        if (lane == 31) wf[warp] = sv;
        __syncthreads();
        if (warp == 0) {
            float wv = wf[lane];
#pragma unroll
            for (int off = 1; off < 32; off <<= 1) {
                float nb = __shfl_up_sync(0xFFFFFFFFu, wv, off);
                if (lane >= off) wv += nb;
            }
            wf[lane] = wv;
        }
        __syncthreads();
        float inclf = sv + (warp ? wf[warp - 1] : 0.f);
        const float Z = wf[NWARPS - 1];
        float excl = inclf - tsum;
        hd[2 * t]     = excl;
        hd[2 * t + 1] = excl + a0;
        __syncthreads();

        // top-p keep predicate + exponential race argmax
        const float c1 = (1.f - tp) * Z;   // keep r iff (Z - hd[r]) > c1
        const float* __restrict__ qrow = q + (size_t)row * V;
        float best = -1.f;
        int bidx = 0x7FFFFFFF, brr = 0;
        for (int r = t; r < S; r += NTHREADS) {
            if (r == 0 || (Z - hd[r]) > c1) {
                int id = DIDX(r);
                float qv = qrow[id];
                float ex = -logf(fmaxf(qv, 1e-10f));
                float sc = e[r] / ex;
                if (sc > best || (sc == best && id < bidx)) { best = sc; bidx = id; brr = r; }
            }
        }
#pragma unroll
        for (int off = 16; off; off >>= 1) {
            float ob = __shfl_down_sync(0xFFFFFFFFu, best, off);
            int   oi = __shfl_down_sync(0xFFFFFFFFu, bidx, off);
            int   orr = __shfl_down_sync(0xFFFFFFFFu, brr, off);
            if (ob > best || (ob == best && oi < bidx)) { best = ob; bidx = oi; brr = orr; }
        }
        if (lane == 0) { wf[warp] = best; wi[warp] = bidx; wr[warp] = brr; }
        __syncthreads();
        if (warp == 0) {
            best = wf[lane]; bidx = wi[lane]; brr = wr[lane];
#pragma unroll
            for (int off = 16; off; off >>= 1) {
                float ob = __shfl_down_sync(0xFFFFFFFFu, best, off);
                int   oi = __shfl_down_sync(0xFFFFFFFFu, bidx, off);
                int   orr = __shfl_down_sync(0xFFFFFFFFu, brr, off);
                if (ob > best || (ob == best && oi < bidx)) { best = ob; bidx = oi; brr = orr; }
            }
            if (lane == 0) { s_sampled = bidx; s_rstar = brr; }
        }
        __syncthreads();
        sampled = s_sampled;
        rstar = s_rstar;
    } else {
        sampled = DIDX(0);   // greedy = argmax (min index on ties)
        rstar = 0;
    }

    // rank: count logprob(val) >= logprob(sampled) over candidates
    const float vstar = DVAL(rstar);
    const float tlp = vstar - lZ;
    for (int r = t; r < n; r += NTHREADS) {
        if ((DVAL(r) - lZ) >= tlp) atomicAdd(&s_rank, 1);
    }
    __syncthreads();

    // outputs: [sampled(B)] [out_idx(B*C)] [out_lp(B*C)] [ranks(B)]
    if (t == 0) {
        out[row] = (float)sampled;
        out[(size_t)B + (size_t)row * C] = (float)sampled;
        out[(size_t)B + (size_t)B * C + (size_t)row * C] = tlp;
        out[(size_t)B + 2 * (size_t)B * C + row] = (float)s_rank;
    }
    if (t >= 1 && t < C) {
        int r = t - 1;   // top-(C-1) entries
        unsigned long long kv = DKEY(r);
        out[(size_t)B + (size_t)row * C + t] = (float)(~(unsigned)kv);
        out[(size_t)B + (size_t)B * C + (size_t)row * C + t] = inv_mono((unsigned)(kv >> 32)) - lZ;
    }
#undef DKEY
#undef DVAL
#undef DIDX
}

// ======================================================================
extern "C" void kernel_launch(void* const* d_in, const int* in_sizes, int n_in,
                              void* d_out, int out_size) {
    const float* logits      = (const float*)d_in[0];
    const float* temperature = (const float*)d_in[1];
    const float* min_p       = (const float*)d_in[2];
    const int*   top_k       = (const int*)d_in[3];
    const float* top_p       = (const float*)d_in[4];
    const float* q           = (const float*)d_in[5];

    int B = in_sizes[1];
    int V = in_sizes[0] / B;
    int C = (out_size / B - 2) / 2;   // num_logprobs + 1

    sampler_fused<<<B, NTHREADS>>>(logits, temperature, min_p, top_k, top_p, q,
                                   (float*)d_out, B, V, C);
}

// round 5
// speedup vs baseline: 1.9219x; 1.9219x over previous
#include <cuda_runtime.h>
#include <stdint.h>

#define NTHREADS 1024
#define NWARPS (NTHREADS / 32)
#define HBITS 13
#define NBINS (1 << HBITS)
#define BPT (NBINS / NTHREADS)      // bins per thread = 8
#define CAP 2048                    // candidate buffer per row
#define NEED_S 330                  // suffix target in SAMPLES (1-of-4 subsample)
#define SAMPLING_EPS 1e-5f

// order-preserving float -> uint32 map (and inverse)
__device__ __forceinline__ unsigned mono(float f) {
    unsigned u = __float_as_uint(f);
    return u ^ ((unsigned)(((int)u) >> 31) | 0x80000000u);
}
__device__ __forceinline__ float inv_mono(unsigned m) {
    unsigned u = (m & 0x80000000u) ? (m ^ 0x80000000u) : ~m;
    return __uint_as_float(u);
}

// one bitonic round's register-resident phases (j = jstart..1, jstart<=32).
// thread holds elements a at index i0 = 64*warp+lane, b at i1 = i0+32.
__device__ __forceinline__ void reg_round(unsigned long long& a, unsigned long long& b,
                                          int i0, int i1, int lane, int kk, int jstart) {
    const bool upa = ((i0 & kk) == 0);
    const bool upb = ((i1 & kk) == 0);
#pragma unroll
    for (int j = 32; j >= 1; j >>= 1) {
        if (j > jstart) continue;
        if (j == 32) {
            // in-thread pair (i0, i0+32); lower index is i0 -> direction upa
            unsigned long long lo = a < b ? a : b;
            unsigned long long hi = a < b ? b : a;
            a = upa ? lo : hi;
            b = upa ? hi : lo;
        } else {
            const bool lower = ((lane & j) == 0);
            unsigned long long pa = __shfl_xor_sync(0xFFFFFFFFu, a, j);
            unsigned long long pb = __shfl_xor_sync(0xFFFFFFFFu, b, j);
            bool keepMinA = (lower == upa);
            bool keepMinB = (lower == upb);
            a = keepMinA ? (a < pa ? a : pa) : (a > pa ? a : pa);
            b = keepMinB ? (b < pb ? b : pb) : (b > pb ? b : pb);
        }
    }
}

// ======================================================================
// Fused sampler: per row (1 CTA):
//   pass A (DRAM): branchless max + 1/4-subsampled 13-bit histogram
//   shuffle scans -> candidate threshold
//   pass B (L2-hot): branchless sum-exp + candidate collection
//   hybrid bitonic sort (warp-shuffle inner phases), min-p/top-k/top-p,
//   exponential-race sampling, top-20 logprobs, rank
// ======================================================================
__global__ __launch_bounds__(NTHREADS, 1) void sampler_fused(
    const float* __restrict__ logits,
    const float* __restrict__ temperature,
    const float* __restrict__ min_p,
    const int*   __restrict__ top_k,
    const float* __restrict__ top_p,
    const float* __restrict__ q,
    float* __restrict__ out,
    int B, int V, int C)
{
    const int row = blockIdx.x;
    const int t = threadIdx.x;
    const int lane = t & 31, warp = t >> 5;

    // 32KB buffer: phase A = hist[8192 u32]; phase B+ = key[2048 u64] | e[2048 f32] | hd[2048 f32]
    __shared__ __align__(16) unsigned char sbuf[NBINS * 4];
    __shared__ float wf[NWARPS];
    __shared__ unsigned wu[NWARPS];
    __shared__ int wi[NWARPS], wr[NWARPS];
    __shared__ unsigned s_bin;
    __shared__ int s_cnt, s_m, s_S, s_rank, s_sampled, s_rstar;
    __shared__ float s_stat[2];   // [0]=rmax [1]=logZ

    unsigned* hist = (unsigned*)sbuf;

    if (t == 0) { s_cnt = 0; s_m = 0; s_S = 0; s_rank = 0; s_bin = 0; }
#pragma unroll
    for (int z = t; z < NBINS; z += NTHREADS) hist[z] = 0u;
    __syncthreads();

    const float* __restrict__ x = logits + (size_t)row * V;
    const int V4 = V >> 2;
    const float4* __restrict__ x4 = (const float4*)x;
    const float NEG_INF = __int_as_float(0xff800000);

    // ------------- pass A: branchless max + subsampled histogram -------------
    float m0 = NEG_INF, m1 = NEG_INF, m2 = NEG_INF, m3 = NEG_INF;
    auto procA = [&](float4 v) {
        atomicAdd(&hist[mono(v.x) >> (32 - HBITS)], 1u);   // 1-of-4 subsample
        m0 = fmaxf(m0, v.x); m1 = fmaxf(m1, v.y);
        m2 = fmaxf(m2, v.z); m3 = fmaxf(m3, v.w);
    };
    int i = t;
    for (; i + 3 * NTHREADS < V4; i += 4 * NTHREADS) {
        float4 a = x4[i];
        float4 b = x4[i + NTHREADS];
        float4 c = x4[i + 2 * NTHREADS];
        float4 d = x4[i + 3 * NTHREADS];
        procA(a); procA(b); procA(c); procA(d);
    }
    for (; i < V4; i += NTHREADS) procA(x4[i]);
    for (int j = (V4 << 2) + t; j < V; j += NTHREADS) {
        float v = x[j];
        atomicAdd(&hist[mono(v) >> (32 - HBITS)], 1u);
        m0 = fmaxf(m0, v);
    }

    // block max reduce
    float m = fmaxf(fmaxf(m0, m1), fmaxf(m2, m3));
#pragma unroll
    for (int off = 16; off; off >>= 1)
        m = fmaxf(m, __shfl_xor_sync(0xFFFFFFFFu, m, off));
    if (lane == 0) wf[warp] = m;
    __syncthreads();                       // hist complete + wf visible
    if (warp == 0) {
        float mm = wf[lane];
#pragma unroll
        for (int off = 16; off; off >>= 1)
            mm = fmaxf(mm, __shfl_xor_sync(0xFFFFFFFFu, mm, off));
        if (lane == 0) s_stat[0] = mm;
    }

    // ---------------- threshold from histogram (shuffle suffix scan) ----------
    unsigned csum = 0;
#pragma unroll
    for (int b = 0; b < BPT; b++) csum += hist[t * BPT + b];
    unsigned iv = csum;
#pragma unroll
    for (int off = 1; off < 32; off <<= 1) {
        unsigned nb = __shfl_up_sync(0xFFFFFFFFu, iv, off);
        if (lane >= off) iv += nb;
    }
    if (lane == 31) wu[warp] = iv;
    __syncthreads();                       // also publishes s_stat[0]
    if (warp == 0) {
        unsigned wv = wu[lane];
#pragma unroll
        for (int off = 1; off < 32; off <<= 1) {
            unsigned nb = __shfl_up_sync(0xFFFFFFFFu, wv, off);
            if (lane >= off) wv += nb;
        }
        wu[lane] = wv;
    }
    __syncthreads();
    unsigned incl = iv + (warp ? wu[warp - 1] : 0u);
    unsigned Total = wu[NWARPS - 1];
    unsigned above = Total - incl;         // samples strictly above my chunk
    unsigned acc = above, prev = above;
#pragma unroll
    for (int b = BPT - 1; b >= 0; b--) {
        int bin = t * BPT + b;
        acc += hist[bin];                  // = suffix(bin) in samples
        if (acc >= NEED_S && prev < NEED_S) s_bin = (unsigned)bin;  // unique crossing
        prev = acc;
    }
    __syncthreads();
    const unsigned thr = s_bin << (32 - HBITS);
    const float rmax = s_stat[0];

    // ------- pass B: branchless sum-exp + collect candidates (L2-hot) --------
    unsigned long long* key = (unsigned long long*)sbuf;       // overwrites hist
    float* e  = (float*)(sbuf + CAP * 8);
    float* hd = (float*)(sbuf + CAP * 8 + CAP * 4);

    float s0 = 0.f, s1 = 0.f, s2 = 0.f, s3 = 0.f;
    auto procB = [&](float4 v, int base) {
        s0 += __expf(v.x - rmax); s1 += __expf(v.y - rmax);
        s2 += __expf(v.z - rmax); s3 += __expf(v.w - rmax);
        unsigned u;
        u = mono(v.x); if (u >= thr) { int p = atomicAdd(&s_cnt, 1); if (p < CAP) key[p] = ((unsigned long long)u << 32) | (unsigned)~(unsigned)(base + 0); }
        u = mono(v.y); if (u >= thr) { int p = atomicAdd(&s_cnt, 1); if (p < CAP) key[p] = ((unsigned long long)u << 32) | (unsigned)~(unsigned)(base + 1); }
        u = mono(v.z); if (u >= thr) { int p = atomicAdd(&s_cnt, 1); if (p < CAP) key[p] = ((unsigned long long)u << 32) | (unsigned)~(unsigned)(base + 2); }
        u = mono(v.w); if (u >= thr) { int p = atomicAdd(&s_cnt, 1); if (p < CAP) key[p] = ((unsigned long long)u << 32) | (unsigned)~(unsigned)(base + 3); }
    };
    i = t;
    for (; i + 3 * NTHREADS < V4; i += 4 * NTHREADS) {
        float4 a = x4[i];
        float4 b = x4[i + NTHREADS];
        float4 c = x4[i + 2 * NTHREADS];
        float4 d = x4[i + 3 * NTHREADS];
        procB(a, 4 * i);
        procB(b, 4 * (i + NTHREADS));
        procB(c, 4 * (i + 2 * NTHREADS));
        procB(d, 4 * (i + 3 * NTHREADS));
    }
    for (; i < V4; i += NTHREADS) procB(x4[i], 4 * i);
    for (int j = (V4 << 2) + t; j < V; j += NTHREADS) {
        float v = x[j];
        s0 += __expf(v - rmax);
        unsigned u = mono(v);
        if (u >= thr) { int p = atomicAdd(&s_cnt, 1); if (p < CAP) key[p] = ((unsigned long long)u << 32) | (unsigned)~(unsigned)j; }
    }
    float ssum = (s0 + s1) + (s2 + s3);
#pragma unroll
    for (int off = 16; off; off >>= 1)
        ssum += __shfl_xor_sync(0xFFFFFFFFu, ssum, off);
    if (lane == 0) wf[warp] = ssum;
    __syncthreads();                       // key writes + s_cnt final
    if (t == 0) {
        float stot = 0.f;
#pragma unroll
        for (int w2 = 0; w2 < NWARPS; w2++) stot += wf[w2];
        s_stat[1] = rmax + logf(stot);
    }
    const int n = min(s_cnt, CAP);
    for (int z = n + t; z < CAP; z += NTHREADS) key[z] = 0ULL;  // sentinel
    __syncthreads();
    const float lZ = s_stat[1];

    // ---------------- hybrid bitonic sort (ascending) --------------------------
    const int i0 = 64 * warp + lane;
    const int i1 = i0 + 32;
    {
        unsigned long long a = key[i0], b = key[i1];
        // rounds kk = 2..64 fully register-resident (no barriers)
#pragma unroll
        for (int kk = 2; kk <= 64; kk <<= 1)
            reg_round(a, b, i0, i1, lane, kk, (kk >> 1) > 32 ? 32 : (kk >> 1));
        key[i0] = a; key[i1] = b;
        __syncthreads();
        // rounds kk = 128..CAP: smem phases j>=64, then register phases j<=32
        for (int kk = 128; kk <= CAP; kk <<= 1) {
            for (int j = kk >> 1; j >= 64; j >>= 1) {
#pragma unroll
                for (int w2 = 0; w2 < CAP / NTHREADS; w2++) {
                    int idx = t + w2 * NTHREADS;
                    int l2 = idx ^ j;
                    if (l2 > idx) {
                        unsigned long long av = key[idx], bv = key[l2];
                        bool sw = ((idx & kk) == 0) ? (av > bv) : (av < bv);
                        if (sw) { key[idx] = bv; key[l2] = av; }
                    }
                }
                __syncthreads();
            }
            a = key[i0]; b = key[i1];
            reg_round(a, b, i0, i1, lane, kk, 32);
            key[i0] = a; key[i1] = b;
            __syncthreads();
        }
    }

#define DKEY(r) (key[CAP - 1 - (r)])
#define DVAL(r) inv_mono((unsigned)(DKEY(r) >> 32))
#define DIDX(r) ((int)(~(unsigned)DKEY(r)))

    // ---------------- per-row scalars ----------------
    const float temp = temperature[row];
    const float mp   = min_p[row];
    const float tp   = top_p[row];
    int kk_ = top_k[row];
    kk_ = max(1, min(kk_, V));
    const float t_mp = rmax + temp * logf(mp);   // min-p threshold in logit space

    // m = # min-p survivors among candidates
    for (int r = t; r < n; r += NTHREADS)
        if (DVAL(r) >= t_mp) atomicAdd(&s_m, 1);
    __syncthreads();
    const int mcnt = s_m;

    // S = # survivors after top-k
    if (mcnt >= kk_) {
        float kth = DVAL(kk_ - 1);
        for (int r = t; r < n; r += NTHREADS)
            if (DVAL(r) >= kth) atomicAdd(&s_S, 1);
    }
    __syncthreads();
    const int S = (mcnt >= kk_) ? min(s_S, CAP) : mcnt;

    const bool greedy = (temp < SAMPLING_EPS);
    int sampled, rstar;

    if (!greedy) {
        // softmax numerators over survivors
        const float lt0 = DVAL(0) / temp;
        for (int r = t; r < CAP; r += NTHREADS) {
            float ev = 0.f;
            if (r < S) ev = expf(DVAL(r) / temp - lt0);
            e[r] = ev;
        }
        __syncthreads();

        // exclusive prefix over descending order (shuffle scan)
        float a0 = e[2 * t], a1 = e[2 * t + 1];
        float tsum = a0 + a1;
        float sv = tsum;
#pragma unroll
        for (int off = 1; off < 32; off <<= 1) {
            float nb = __shfl_up_sync(0xFFFFFFFFu, sv, off);
            if (lane >= off) sv += nb;
        }
        if (lane == 31) wf[warp] = sv;
        __syncthreads();
        if (warp == 0) {
            float wv = wf[lane];
#pragma unroll
            for (int off = 1; off < 32; off <<= 1) {
                float nb = __shfl_up_sync(0xFFFFFFFFu, wv, off);
                if (lane >= off) wv += nb;
            }
            wf[lane] = wv;
        }
        __syncthreads();
        float inclf = sv + (warp ? wf[warp - 1] : 0.f);
        const float Z = wf[NWARPS - 1];
        float excl = inclf - tsum;
        hd[2 * t]     = excl;
        hd[2 * t + 1] = excl + a0;
        __syncthreads();

        // top-p keep predicate + exponential race argmax
        const float c1 = (1.f - tp) * Z;   // keep r iff (Z - hd[r]) > c1
        const float* __restrict__ qrow = q + (size_t)row * V;
        float best = -1.f;
        int bidx = 0x7FFFFFFF, brr = 0;
        for (int r = t; r < S; r += NTHREADS) {
            if (r == 0 || (Z - hd[r]) > c1) {
                int id = DIDX(r);
                float qv = qrow[id];
                float ex = -logf(fmaxf(qv, 1e-10f));
                float sc = e[r] / ex;
                if (sc > best || (sc == best && id < bidx)) { best = sc; bidx = id; brr = r; }
            }
        }
#pragma unroll
        for (int off = 16; off; off >>= 1) {
            float ob = __shfl_down_sync(0xFFFFFFFFu, best, off);
            int   oi = __shfl_down_sync(0xFFFFFFFFu, bidx, off);
            int   orr = __shfl_down_sync(0xFFFFFFFFu, brr, off);
            if (ob > best || (ob == best && oi < bidx)) { best = ob; bidx = oi; brr = orr; }
        }
        if (lane == 0) { wf[warp] = best; wi[warp] = bidx; wr[warp] = brr; }
        __syncthreads();
        if (warp == 0) {
            best = wf[lane]; bidx = wi[lane]; brr = wr[lane];
#pragma unroll
            for (int off = 16; off; off >>= 1) {
                float ob = __shfl_down_sync(0xFFFFFFFFu, best, off);
                int   oi = __shfl_down_sync(0xFFFFFFFFu, bidx, off);
                int   orr = __shfl_down_sync(0xFFFFFFFFu, brr, off);
                if (ob > best || (ob == best && oi < bidx)) { best = ob; bidx = oi; brr = orr; }
            }
            if (lane == 0) { s_sampled = bidx; s_rstar = brr; }
        }
        __syncthreads();
        sampled = s_sampled;
        rstar = s_rstar;
    } else {
        sampled = DIDX(0);   // greedy = argmax (min index on ties)
        rstar = 0;
    }

    // rank: count logprob(val) >= logprob(sampled) over candidates
    const float vstar = DVAL(rstar);
    const float tlp = vstar - lZ;
    for (int r = t; r < n; r += NTHREADS) {
        if ((DVAL(r) - lZ) >= tlp) atomicAdd(&s_rank, 1);
    }
    __syncthreads();

    // outputs: [sampled(B)] [out_idx(B*C)] [out_lp(B*C)] [ranks(B)]
    if (t == 0) {
        out[row] = (float)sampled;
        out[(size_t)B + (size_t)row * C] = (float)sampled;
        out[(size_t)B + (size_t)B * C + (size_t)row * C] = tlp;
        out[(size_t)B + 2 * (size_t)B * C + row] = (float)s_rank;
    }
    if (t >= 1 && t < C) {
        int r = t - 1;   // top-(C-1) entries
        unsigned long long kv = DKEY(r);
        out[(size_t)B + (size_t)row * C + t] = (float)(~(unsigned)kv);
        out[(size_t)B + (size_t)B * C + (size_t)row * C + t] = inv_mono((unsigned)(kv >> 32)) - lZ;
    }
#undef DKEY
#undef DVAL
#undef DIDX
}

// ======================================================================
extern "C" void kernel_launch(void* const* d_in, const int* in_sizes, int n_in,
                              void* d_out, int out_size) {
    const float* logits      = (const float*)d_in[0];
    const float* temperature = (const float*)d_in[1];
    const float* min_p       = (const float*)d_in[2];
    const int*   top_k       = (const int*)d_in[3];
    const float* top_p       = (const float*)d_in[4];
    const float* q           = (const float*)d_in[5];

    int B = in_sizes[1];
    int V = in_sizes[0] / B;
    int C = (out_size / B - 2) / 2;   // num_logprobs + 1

    sampler_fused<<<B, NTHREADS>>>(logits, temperature, min_p, top_k, top_p, q,
                                   (float*)d_out, B, V, C);
}